// round 10
// baseline (speedup 1.0000x reference)
#include <cuda_runtime.h>
#include <cuda_bf16.h>
#include <cuda_fp16.h>
#include <cstdint>
#include <cstddef>

#define NN 100000
#define EE 1600000
#define C  128
#define NB 98                 // scan blocks: ceil(100000/1024)
#define NP (NN + 128)         // padded rows so edge-tile cp.async stays in-bounds

// ---- scratch (device globals: allocation-free) ----
// hi/lo bf16 split tables (A operands of the GEMMs)
__device__ __nv_bfloat16 g_agghi[(size_t)NP * C];
__device__ __nv_bfloat16 g_agglo[(size_t)NP * C];
__device__ __nv_bfloat16 g_xhi [(size_t)NP * C];
__device__ __nv_bfloat16 g_xlo [(size_t)NP * C];
__device__ __nv_bfloat16 g_h1hi[(size_t)NP * C];
__device__ __nv_bfloat16 g_h1lo[(size_t)NP * C];
__device__ __nv_bfloat16 g_h2hi[(size_t)NP * C];
__device__ __nv_bfloat16 g_h2lo[(size_t)NP * C];
// fp16 gather tables (aggregation sources)
__device__ __half g_xh [(size_t)NN * C];
__device__ __half g_h1h[(size_t)NN * C];
// CSR
__device__ int g_cnt[NN];
__device__ int g_rowptr[NN + 1];
__device__ int g_cursor[NN];
__device__ int g_part[NB];
__device__ int g_srcs[EE];
// weights
__device__ __nv_bfloat16 g_whi[6 * 16384];
__device__ __nv_bfloat16 g_wlo[6 * 16384];

// ---------------------------------------------------------------------------
// helpers
// ---------------------------------------------------------------------------
__device__ __forceinline__ uint32_t smem_u32(const void* p) {
    uint32_t a;
    asm("{ .reg .u64 t; cvta.to.shared.u64 t, %1; cvt.u32.u64 %0, t; }"
        : "=r"(a) : "l"(p));
    return a;
}
__device__ __forceinline__ void cp16(uint32_t saddr, const void* g) {
    asm volatile("cp.async.cg.shared.global [%0], [%1], 16;"
                 :: "r"(saddr), "l"(g) : "memory");
}
__device__ __forceinline__ void ldsm4(uint32_t addr, uint32_t* r) {
    asm volatile("ldmatrix.sync.aligned.m8n8.x4.shared.b16 {%0,%1,%2,%3}, [%4];"
                 : "=r"(r[0]), "=r"(r[1]), "=r"(r[2]), "=r"(r[3]) : "r"(addr));
}
__device__ __forceinline__ void mma16816(float* c, const uint32_t* a, const uint32_t* b) {
    asm volatile(
        "mma.sync.aligned.m16n8k16.row.col.f32.bf16.bf16.f32 "
        "{%0,%1,%2,%3}, {%4,%5,%6,%7}, {%8,%9}, {%0,%1,%2,%3};"
        : "+f"(c[0]), "+f"(c[1]), "+f"(c[2]), "+f"(c[3])
        : "r"(a[0]), "r"(a[1]), "r"(a[2]), "r"(a[3]), "r"(b[0]), "r"(b[1]));
}
__device__ __forceinline__ uint32_t packbf2(float f0, float f1) {
    uint32_t r;
    asm("cvt.rn.bf16x2.f32 %0, %1, %2;" : "=r"(r) : "f"(f1), "f"(f0));
    return r;
}
// split (f0,f1) -> hi bf16x2 + lo bf16x2
__device__ __forceinline__ void split2(float f0, float f1, uint32_t& h, uint32_t& l) {
    h = packbf2(f0, f1);
    float l0 = f0 - __uint_as_float(h << 16);
    float l1 = f1 - __uint_as_float(h & 0xFFFF0000u);
    l = packbf2(l0, l1);
}
__device__ __forceinline__ int warp_iscan(int v, int lane) {
#pragma unroll
    for (int d = 1; d < 32; d <<= 1) {
        int n = __shfl_up_sync(0xFFFFFFFFu, v, d);
        if (lane >= d) v += n;
    }
    return v;
}

// ---------------------------------------------------------------------------
// zero fill
// ---------------------------------------------------------------------------
__global__ void zero_i(int* __restrict__ p, int n) {
    int i = blockIdx.x * blockDim.x + threadIdx.x;
    if (i < n) p[i] = 0;
}

// ---------------------------------------------------------------------------
// one-shot x prep: fp32 -> fp16 gather table + hi/lo bf16 tables
// ---------------------------------------------------------------------------
__global__ void split_feat(const float* __restrict__ src,
                           __half* __restrict__ fh,
                           __nv_bfloat16* __restrict__ hi,
                           __nv_bfloat16* __restrict__ lo, int n4)
{
    int i = blockIdx.x * blockDim.x + threadIdx.x;
    if (i >= n4) return;
    float4 v = __ldg((const float4*)src + i);
    __half2 p0 = __floats2half2_rn(v.x, v.y);
    __half2 p1 = __floats2half2_rn(v.z, v.w);
    *(uint2*)(fh + (size_t)i * 4) = make_uint2(*(uint32_t*)&p0, *(uint32_t*)&p1);
    uint32_t h0, l0, h1, l1;
    split2(v.x, v.y, h0, l0);
    split2(v.z, v.w, h1, l1);
    *(uint2*)(hi + (size_t)i * 4) = make_uint2(h0, h1);
    *(uint2*)(lo + (size_t)i * 4) = make_uint2(l0, l1);
}

// ---------------------------------------------------------------------------
// one-shot weight split
// ---------------------------------------------------------------------------
__global__ void split_weights(const float* __restrict__ Wl1, const float* __restrict__ Wr1,
                              const float* __restrict__ Wl2, const float* __restrict__ Wr2,
                              const float* __restrict__ Wlin,
                              __nv_bfloat16* __restrict__ whi,
                              __nv_bfloat16* __restrict__ wlo)
{
    int i = blockIdx.x * blockDim.x + threadIdx.x;
    if (i >= 6 * 16384) return;
    int s = i >> 14, r = (i >> 7) & 127, k = i & 127;
    float v;
    switch (s) {
        case 0:  v = __ldg(Wl1 + r * 128 + k); break;
        case 1:  v = __ldg(Wr1 + r * 128 + k); break;
        case 2:  v = __ldg(Wl2 + r * 128 + k); break;
        case 3:  v = __ldg(Wr2 + r * 128 + k); break;
        case 4:  v = __ldg(Wlin + r * 256 + k); break;
        default: v = __ldg(Wlin + r * 256 + 128 + k); break;
    }
    __nv_bfloat16 h = __float2bfloat16(v);
    whi[i] = h;
    wlo[i] = __float2bfloat16(v - __bfloat162float(h));
}

// ---------------------------------------------------------------------------
// CSR build: histogram -> 3-phase scan -> bucket scatter
// ---------------------------------------------------------------------------
__global__ void hist_kernel(const int* __restrict__ dst, int* __restrict__ cnt) {
    int e = blockIdx.x * blockDim.x + threadIdx.x;
    if (e < EE) atomicAdd(cnt + __ldg(dst + e), 1);
}

__global__ __launch_bounds__(1024) void scan_blk(
    const int* __restrict__ cnt, int* __restrict__ rowptr, int* __restrict__ part)
{
    __shared__ int ws[32];
    const int t = threadIdx.x, lane = t & 31, w = t >> 5;
    const int i = blockIdx.x * 1024 + t;
    const int v = (i < NN) ? __ldg(cnt + i) : 0;

    int x = warp_iscan(v, lane);
    if (lane == 31) ws[w] = x;
    __syncthreads();
    if (w == 0) ws[lane] = warp_iscan(ws[lane], lane);
    __syncthreads();

    const int incl = x + (w ? ws[w - 1] : 0);
    if (i < NN) rowptr[i] = incl - v;
    if (t == 1023) part[blockIdx.x] = incl;
}

__global__ __launch_bounds__(128) void scan_part(int* __restrict__ part) {
    __shared__ int ws[4];
    const int t = threadIdx.x, lane = t & 31, w = t >> 5;
    const int v = (t < NB) ? part[t] : 0;
    int x = warp_iscan(v, lane);
    if (lane == 31) ws[w] = x;
    __syncthreads();
    if (t == 0) {
        int run = 0;
        for (int j = 0; j < 4; j++) { int s = ws[j]; ws[j] = run; run += s; }
    }
    __syncthreads();
    if (t < NB) part[t] = x - v + ws[w];
}

__global__ __launch_bounds__(1024) void scan_add(
    const int* __restrict__ part, int* __restrict__ rowptr, int* __restrict__ cursor)
{
    const int i = blockIdx.x * 1024 + threadIdx.x;
    if (i < NN) {
        int r = rowptr[i] + part[blockIdx.x];
        rowptr[i] = r;
        cursor[i] = r;
    }
    if (i == 0) rowptr[NN] = EE;
}

__global__ void scatter_csr(const int* __restrict__ src, const int* __restrict__ dst,
                            int* __restrict__ cursor, int* __restrict__ srcs)
{
    int e = blockIdx.x * blockDim.x + threadIdx.x;
    if (e >= EE) return;
    int d = __ldg(dst + e);
    int pos = atomicAdd(cursor + d, 1);
    srcs[pos] = __ldg(src + e);
}

// ---------------------------------------------------------------------------
// atomic-free mean aggregation from fp16 table; writes hi/lo bf16 split
// ---------------------------------------------------------------------------
__global__ __launch_bounds__(256) void aggregate_h(
    const __half* __restrict__ feat16,
    const int*    __restrict__ rowptr,
    const int*    __restrict__ srcs,
    __nv_bfloat16* __restrict__ agghi,
    __nv_bfloat16* __restrict__ agglo)
{
    const int node = blockIdx.x * 8 + (threadIdx.x >> 5);
    const int lane = threadIdx.x & 31;
    if (node >= NN) return;

    const int beg = __ldg(rowptr + node);
    const int end = __ldg(rowptr + node + 1);

    const uint2* fb = (const uint2*)feat16 + lane;   // row = 32 uint2

    float a0 = 0.f, a1 = 0.f, a2 = 0.f, a3 = 0.f;
    int e = beg;
    for (; e + 4 <= end; e += 4) {
        int s0 = __ldg(srcs + e);
        int s1 = __ldg(srcs + e + 1);
        int s2 = __ldg(srcs + e + 2);
        int s3 = __ldg(srcs + e + 3);
        uint2 u0 = __ldg(fb + (size_t)s0 * 32);
        uint2 u1 = __ldg(fb + (size_t)s1 * 32);
        uint2 u2 = __ldg(fb + (size_t)s2 * 32);
        uint2 u3 = __ldg(fb + (size_t)s3 * 32);
#pragma unroll
        for (int j = 0; j < 4; j++) {
            uint2 u = (j == 0) ? u0 : (j == 1) ? u1 : (j == 2) ? u2 : u3;
            float2 f0 = __half22float2(*(__half2*)&u.x);
            float2 f1 = __half22float2(*(__half2*)&u.y);
            a0 += f0.x; a1 += f0.y; a2 += f1.x; a3 += f1.y;
        }
    }
    for (; e < end; e++) {
        int s0 = __ldg(srcs + e);
        uint2 u = __ldg(fb + (size_t)s0 * 32);
        float2 f0 = __half22float2(*(__half2*)&u.x);
        float2 f1 = __half22float2(*(__half2*)&u.y);
        a0 += f0.x; a1 += f0.y; a2 += f1.x; a3 += f1.y;
    }

    const int deg = end - beg;
    const float inv = 1.f / (float)(deg > 1 ? deg : 1);
    a0 *= inv; a1 *= inv; a2 *= inv; a3 *= inv;

    uint32_t h0, l0, h1, l1;
    split2(a0, a1, h0, l0);
    split2(a2, a3, h1, l1);
    const size_t off = (size_t)node * C + lane * 4;
    *(uint2*)(agghi + off) = make_uint2(h0, h1);
    *(uint2*)(agglo + off) = make_uint2(l0, l1);
}

// ---------------------------------------------------------------------------
// HMMA fused dual-matmul layer; all operands pre-split hi/lo bf16 in global.
//   acc = A1·W{s0} + A2·W{s1} (emulated fp32: Ah·Wh + Al·Wh + Ah·Wl)
// Staging is pure cp.async for both A and W slabs.
// Epilogue: bias+relu -> any of {fp32 out, fp16 mirror, hi/lo bf16 tables}.
// ---------------------------------------------------------------------------
#define PITCH  72
#define SLAB_B (128 * PITCH * 2)
#define AH_OFF 0
#define AL_OFF SLAB_B
#define WH_OFF (2 * SLAB_B)
#define WL_OFF (3 * SLAB_B)
#define SMEM_BYTES (4 * SLAB_B)         // 73728

__global__ __launch_bounds__(256, 2) void hmma_layer(
    const __nv_bfloat16* __restrict__ a1hi, const __nv_bfloat16* __restrict__ a1lo,
    const __nv_bfloat16* __restrict__ a2hi, const __nv_bfloat16* __restrict__ a2lo,
    const __nv_bfloat16* __restrict__ whi,  const __nv_bfloat16* __restrict__ wlo,
    int s0, int s1,
    const float* __restrict__ bias,
    float* __restrict__ out32, __half* __restrict__ outh,
    __nv_bfloat16* __restrict__ outhi, __nv_bfloat16* __restrict__ outlo,
    int nrows)
{
    extern __shared__ char sm[];
    const uint32_t smb = smem_u32(sm);
    const int t = threadIdx.x, wid = t >> 5, lane = t & 31;
    const int nb = blockIdx.x * 128;

    const int mBase = (wid & 3) * 32;
    const int nBase = (wid >> 2) * 64;

    const int arow = (lane & 7) + ((lane >> 3) & 1) * 8;
    const int acol = (lane >> 4) * 8;
    const int brow = (lane & 7) + (lane >> 4) * 8;
    const int bcol = ((lane >> 3) & 1) * 8;
    const uint32_t aoff0 = ((mBase + arow) * PITCH + acol) * 2;
    const uint32_t aoff1 = aoff0 + 16 * PITCH * 2;
    const uint32_t boff  = ((nBase + brow) * PITCH + bcol) * 2;

    float acc[2][8][4];
#pragma unroll
    for (int mt = 0; mt < 2; mt++)
#pragma unroll
        for (int nt = 0; nt < 8; nt++)
#pragma unroll
            for (int j = 0; j < 4; j++) acc[mt][nt][j] = 0.f;

#pragma unroll 1
    for (int pass = 0; pass < 2; pass++) {
        const __nv_bfloat16* Ah = pass ? a2hi : a1hi;
        const __nv_bfloat16* Al = pass ? a2lo : a1lo;
        const __nv_bfloat16* Wh = whi + (size_t)(pass ? s1 : s0) * 16384;
        const __nv_bfloat16* Wl = wlo + (size_t)(pass ? s1 : s0) * 16384;

#pragma unroll 1
        for (int chunk = 0; chunk < 2; chunk++) {
            const int k0 = chunk * 64;

            // A slabs (hi/lo) via cp.async
            for (int i = t; i < 2048; i += 256) {
                const int slab = i >> 10;
                const int r    = (i >> 3) & 127;
                const int seg  = i & 7;
                const uint32_t sa = smb + (slab ? AL_OFF : AH_OFF)
                                  + r * (PITCH * 2) + seg * 16;
                const __nv_bfloat16* g = (slab ? Al : Ah)
                                       + (size_t)(nb + r) * C + k0 + seg * 8;
                cp16(sa, g);
            }
            // W slabs (hi/lo) via cp.async
            for (int i = t; i < 2048; i += 256) {
                const int slab = i >> 10;
                const int r    = (i >> 3) & 127;
                const int seg  = i & 7;
                const uint32_t sa = smb + (slab ? WL_OFF : WH_OFF)
                                  + r * (PITCH * 2) + seg * 16;
                const __nv_bfloat16* g = (slab ? Wl : Wh) + (size_t)r * 128 + k0 + seg * 8;
                cp16(sa, g);
            }
            asm volatile("cp.async.commit_group;" ::: "memory");
            asm volatile("cp.async.wait_group 0;" ::: "memory");
            __syncthreads();

#pragma unroll
            for (int ks = 0; ks < 4; ks++) {
                uint32_t ah0[4], ah1[4], al0[4], al1[4];
                ldsm4(smb + AH_OFF + aoff0 + ks * 32, ah0);
                ldsm4(smb + AH_OFF + aoff1 + ks * 32, ah1);
                ldsm4(smb + AL_OFF + aoff0 + ks * 32, al0);
                ldsm4(smb + AL_OFF + aoff1 + ks * 32, al1);
#pragma unroll
                for (int p = 0; p < 4; p++) {
                    uint32_t bh[4], bl[4];
                    const uint32_t bo = boff + p * (16 * PITCH * 2) + ks * 32;
                    ldsm4(smb + WH_OFF + bo, bh);
                    ldsm4(smb + WL_OFF + bo, bl);
                    mma16816(acc[0][2 * p],     ah0, bh);
                    mma16816(acc[1][2 * p],     ah1, bh);
                    mma16816(acc[0][2 * p],     al0, bh);
                    mma16816(acc[1][2 * p],     al1, bh);
                    mma16816(acc[0][2 * p],     ah0, bl);
                    mma16816(acc[1][2 * p],     ah1, bl);
                    mma16816(acc[0][2 * p + 1], ah0, bh + 2);
                    mma16816(acc[1][2 * p + 1], ah1, bh + 2);
                    mma16816(acc[0][2 * p + 1], al0, bh + 2);
                    mma16816(acc[1][2 * p + 1], al1, bh + 2);
                    mma16816(acc[0][2 * p + 1], ah0, bl + 2);
                    mma16816(acc[1][2 * p + 1], ah1, bl + 2);
                }
            }
            __syncthreads();
        }
    }

    // -- epilogue: bias + relu --
    const int qrow = lane >> 2;
    const int qk   = (lane & 3) * 2;
#pragma unroll
    for (int nt = 0; nt < 8; nt++) {
        const int cl = nBase + nt * 8 + qk;
        const float2 b = __ldg((const float2*)(bias + cl));
#pragma unroll
        for (int mt = 0; mt < 2; mt++) {
#pragma unroll
            for (int half = 0; half < 2; half++) {
                const int r = nb + mBase + mt * 16 + qrow + half * 8;
                if (r < nrows) {
                    float ox = fmaxf(acc[mt][nt][2 * half]     + b.x, 0.f);
                    float oy = fmaxf(acc[mt][nt][2 * half + 1] + b.y, 0.f);
                    const size_t off = (size_t)r * C + cl;
                    if (out32) *(float2*)(out32 + off) = make_float2(ox, oy);
                    if (outh) {
                        __half2 hh = __floats2half2_rn(ox, oy);
                        *(__half2*)(outh + off) = hh;
                    }
                    if (outhi) {
                        uint32_t h, l;
                        split2(ox, oy, h, l);
                        *(uint32_t*)(outhi + off) = h;
                        *(uint32_t*)(outlo + off) = l;
                    }
                }
            }
        }
    }
}

// ---------------------------------------------------------------------------
// launch
// ---------------------------------------------------------------------------
extern "C" void kernel_launch(void* const* d_in, const int* in_sizes, int n_in,
                              void* d_out, int out_size)
{
    const float* x    = (const float*)d_in[0];
    const int*   ei   = (const int*)  d_in[1];
    const float* Wl1  = (const float*)d_in[2];
    const float* Wr1  = (const float*)d_in[3];
    const float* b1   = (const float*)d_in[4];
    const float* Wl2  = (const float*)d_in[5];
    const float* Wr2  = (const float*)d_in[6];
    const float* b2   = (const float*)d_in[7];
    const float* Wlin = (const float*)d_in[8];
    const float* blin = (const float*)d_in[9];
    float*       out  = (float*)d_out;

    const int* src = ei;
    const int* dst = ei + EE;

    void *agghi_v, *agglo_v, *xhi_v, *xlo_v, *h1hi_v, *h1lo_v, *h2hi_v, *h2lo_v;
    void *xh_v, *h1h_v, *cnt_v, *rp_v, *cur_v, *part_v, *srcs_v, *whi_v, *wlo_v;
    cudaGetSymbolAddress(&agghi_v, g_agghi);
    cudaGetSymbolAddress(&agglo_v, g_agglo);
    cudaGetSymbolAddress(&xhi_v,  g_xhi);
    cudaGetSymbolAddress(&xlo_v,  g_xlo);
    cudaGetSymbolAddress(&h1hi_v, g_h1hi);
    cudaGetSymbolAddress(&h1lo_v, g_h1lo);
    cudaGetSymbolAddress(&h2hi_v, g_h2hi);
    cudaGetSymbolAddress(&h2lo_v, g_h2lo);
    cudaGetSymbolAddress(&xh_v,   g_xh);
    cudaGetSymbolAddress(&h1h_v,  g_h1h);
    cudaGetSymbolAddress(&cnt_v,  g_cnt);
    cudaGetSymbolAddress(&rp_v,   g_rowptr);
    cudaGetSymbolAddress(&cur_v,  g_cursor);
    cudaGetSymbolAddress(&part_v, g_part);
    cudaGetSymbolAddress(&srcs_v, g_srcs);
    cudaGetSymbolAddress(&whi_v,  g_whi);
    cudaGetSymbolAddress(&wlo_v,  g_wlo);
    __nv_bfloat16* agghi = (__nv_bfloat16*)agghi_v;
    __nv_bfloat16* agglo = (__nv_bfloat16*)agglo_v;
    __nv_bfloat16* xhi   = (__nv_bfloat16*)xhi_v;
    __nv_bfloat16* xlo   = (__nv_bfloat16*)xlo_v;
    __nv_bfloat16* h1hi  = (__nv_bfloat16*)h1hi_v;
    __nv_bfloat16* h1lo  = (__nv_bfloat16*)h1lo_v;
    __nv_bfloat16* h2hi  = (__nv_bfloat16*)h2hi_v;
    __nv_bfloat16* h2lo  = (__nv_bfloat16*)h2lo_v;
    __half* xh  = (__half*)xh_v;
    __half* h1h = (__half*)h1h_v;
    int* cnt    = (int*)cnt_v;
    int* rowptr = (int*)rp_v;
    int* cursor = (int*)cur_v;
    int* part   = (int*)part_v;
    int* srcs   = (int*)srcs_v;
    __nv_bfloat16* whi = (__nv_bfloat16*)whi_v;
    __nv_bfloat16* wlo = (__nv_bfloat16*)wlo_v;

    cudaFuncSetAttribute(hmma_layer,
                         cudaFuncAttributeMaxDynamicSharedMemorySize, SMEM_BYTES);

    const int eblk = (EE + 255) / 256;          // 6250
    const int gblk = (NN + 127) / 128;          // 782
    const int ablk = (NN + 7) / 8;              // 12500
    const int wblk = (6 * 16384 + 255) / 256;
    const int n4   = NN * C / 4;                // 3,200,000
    const int fblk = (n4 + 255) / 256;

    // ---- prep: weight split + x tables + CSR build ----
    split_weights<<<wblk, 256>>>(Wl1, Wr1, Wl2, Wr2, Wlin, whi, wlo);
    split_feat<<<fblk, 256>>>(x, xh, xhi, xlo, n4);
    zero_i<<<(NN + 255) / 256, 256>>>(cnt, NN);
    hist_kernel<<<eblk, 256>>>(dst, cnt);
    scan_blk<<<NB, 1024>>>(cnt, rowptr, part);
    scan_part<<<1, 128>>>(part);
    scan_add<<<NB, 1024>>>(part, rowptr, cursor);
    scatter_csr<<<eblk, 256>>>(src, dst, cursor, srcs);

    // ---- conv1: gather16(x) -> agg(hi/lo); h1 = relu(agg·Wl1 + x·Wr1 + b1) ----
    aggregate_h<<<ablk, 256>>>(xh, rowptr, srcs, agghi, agglo);
    hmma_layer<<<gblk, 256, SMEM_BYTES>>>(agghi, agglo, xhi, xlo, whi, wlo, 0, 1,
                                          b1, nullptr, h1h, h1hi, h1lo, NN);

    // ---- conv2: gather16(h1) -> agg(hi/lo); h2 = relu(agg·Wl2 + h1·Wr2 + b2) ----
    aggregate_h<<<ablk, 256>>>(h1h, rowptr, srcs, agghi, agglo);
    hmma_layer<<<gblk, 256, SMEM_BYTES>>>(agghi, agglo, h1hi, h1lo, whi, wlo, 2, 3,
                                          b2, nullptr, nullptr, h2hi, h2lo, NN);

    // ---- JK-cat + linear head: out = relu(h1·Wlin[:, :128] + h2·Wlin[:, 128:] + blin) ----
    hmma_layer<<<gblk, 256, SMEM_BYTES>>>(h1hi, h1lo, h2hi, h2lo, whi, wlo, 4, 5,
                                          blin, out, nullptr, nullptr, nullptr, NN);
}

// round 11
// speedup vs baseline: 1.5660x; 1.5660x over previous
#include <cuda_runtime.h>
#include <cuda_fp16.h>
#include <cstdint>
#include <cstddef>

#define NN 100000
#define EE 1600000
#define C  128
#define NB 98                 // scan blocks: ceil(100000/1024)
#define NP (NN + 128)         // padded rows: edge-tile cp.async stays in-bounds

// ---- scratch (device globals: allocation-free) ----
// unified fp16 tables: gather source AND GEMM operand
__device__ __half g_xh  [(size_t)NP * C];
__device__ __half g_aggh[(size_t)NP * C];
__device__ __half g_h1h [(size_t)NP * C];
__device__ __half g_h2h [(size_t)NP * C];
// fp16 weights: 6 slabs of [128][128]
__device__ __half g_wh[6 * 16384];
// CSR
__device__ int g_cnt[NN];
__device__ int g_rowptr[NN + 1];
__device__ int g_cursor[NN];
__device__ int g_part[NB];
__device__ int g_srcs[EE];

// ---------------------------------------------------------------------------
// helpers
// ---------------------------------------------------------------------------
__device__ __forceinline__ uint32_t smem_u32(const void* p) {
    uint32_t a;
    asm("{ .reg .u64 t; cvta.to.shared.u64 t, %1; cvt.u32.u64 %0, t; }"
        : "=r"(a) : "l"(p));
    return a;
}
__device__ __forceinline__ void cp16(uint32_t saddr, const void* g) {
    asm volatile("cp.async.cg.shared.global [%0], [%1], 16;"
                 :: "r"(saddr), "l"(g) : "memory");
}
__device__ __forceinline__ void ldsm4(uint32_t addr, uint32_t* r) {
    asm volatile("ldmatrix.sync.aligned.m8n8.x4.shared.b16 {%0,%1,%2,%3}, [%4];"
                 : "=r"(r[0]), "=r"(r[1]), "=r"(r[2]), "=r"(r[3]) : "r"(addr));
}
__device__ __forceinline__ void mma16816h(float* c, const uint32_t* a, const uint32_t* b) {
    asm volatile(
        "mma.sync.aligned.m16n8k16.row.col.f32.f16.f16.f32 "
        "{%0,%1,%2,%3}, {%4,%5,%6,%7}, {%8,%9}, {%0,%1,%2,%3};"
        : "+f"(c[0]), "+f"(c[1]), "+f"(c[2]), "+f"(c[3])
        : "r"(a[0]), "r"(a[1]), "r"(a[2]), "r"(a[3]), "r"(b[0]), "r"(b[1]));
}
__device__ __forceinline__ int warp_iscan(int v, int lane) {
#pragma unroll
    for (int d = 1; d < 32; d <<= 1) {
        int n = __shfl_up_sync(0xFFFFFFFFu, v, d);
        if (lane >= d) v += n;
    }
    return v;
}

// ---------------------------------------------------------------------------
// zero fill / prep conversions
// ---------------------------------------------------------------------------
__global__ void zero_i(int* __restrict__ p, int n) {
    int i = blockIdx.x * blockDim.x + threadIdx.x;
    if (i < n) p[i] = 0;
}

__global__ void to_half_feat(const float* __restrict__ src, __half* __restrict__ dst, int n4) {
    int i = blockIdx.x * blockDim.x + threadIdx.x;
    if (i >= n4) return;
    float4 v = __ldg((const float4*)src + i);
    __half2 h0 = __floats2half2_rn(v.x, v.y);
    __half2 h1 = __floats2half2_rn(v.z, v.w);
    *(uint2*)(dst + (size_t)i * 4) = make_uint2(*(uint32_t*)&h0, *(uint32_t*)&h1);
}

__global__ void weights_h(const float* __restrict__ Wl1, const float* __restrict__ Wr1,
                          const float* __restrict__ Wl2, const float* __restrict__ Wr2,
                          const float* __restrict__ Wlin, __half* __restrict__ wh)
{
    int i = blockIdx.x * blockDim.x + threadIdx.x;
    if (i >= 6 * 16384) return;
    int s = i >> 14, r = (i >> 7) & 127, k = i & 127;
    float v;
    switch (s) {
        case 0:  v = __ldg(Wl1 + r * 128 + k); break;
        case 1:  v = __ldg(Wr1 + r * 128 + k); break;
        case 2:  v = __ldg(Wl2 + r * 128 + k); break;
        case 3:  v = __ldg(Wr2 + r * 128 + k); break;
        case 4:  v = __ldg(Wlin + r * 256 + k); break;
        default: v = __ldg(Wlin + r * 256 + 128 + k); break;
    }
    wh[i] = __float2half_rn(v);
}

// ---------------------------------------------------------------------------
// CSR build: histogram -> 3-phase scan -> bucket scatter
// ---------------------------------------------------------------------------
__global__ void hist_kernel(const int* __restrict__ dst, int* __restrict__ cnt) {
    int e = blockIdx.x * blockDim.x + threadIdx.x;
    if (e < EE) atomicAdd(cnt + __ldg(dst + e), 1);
}

__global__ __launch_bounds__(1024) void scan_blk(
    const int* __restrict__ cnt, int* __restrict__ rowptr, int* __restrict__ part)
{
    __shared__ int ws[32];
    const int t = threadIdx.x, lane = t & 31, w = t >> 5;
    const int i = blockIdx.x * 1024 + t;
    const int v = (i < NN) ? __ldg(cnt + i) : 0;

    int x = warp_iscan(v, lane);
    if (lane == 31) ws[w] = x;
    __syncthreads();
    if (w == 0) ws[lane] = warp_iscan(ws[lane], lane);
    __syncthreads();

    const int incl = x + (w ? ws[w - 1] : 0);
    if (i < NN) rowptr[i] = incl - v;
    if (t == 1023) part[blockIdx.x] = incl;
}

__global__ __launch_bounds__(128) void scan_part(int* __restrict__ part) {
    __shared__ int ws[4];
    const int t = threadIdx.x, lane = t & 31, w = t >> 5;
    const int v = (t < NB) ? part[t] : 0;
    int x = warp_iscan(v, lane);
    if (lane == 31) ws[w] = x;
    __syncthreads();
    if (t == 0) {
        int run = 0;
        for (int j = 0; j < 4; j++) { int s = ws[j]; ws[j] = run; run += s; }
    }
    __syncthreads();
    if (t < NB) part[t] = x - v + ws[w];
}

__global__ __launch_bounds__(1024) void scan_add(
    const int* __restrict__ part, int* __restrict__ rowptr, int* __restrict__ cursor)
{
    const int i = blockIdx.x * 1024 + threadIdx.x;
    if (i < NN) {
        int r = rowptr[i] + part[blockIdx.x];
        rowptr[i] = r;
        cursor[i] = r;
    }
    if (i == 0) rowptr[NN] = EE;
}

__global__ void scatter_csr(const int* __restrict__ src, const int* __restrict__ dst,
                            int* __restrict__ cursor, int* __restrict__ srcs)
{
    int e = blockIdx.x * blockDim.x + threadIdx.x;
    if (e >= EE) return;
    int d = __ldg(dst + e);
    int pos = atomicAdd(cursor + d, 1);
    srcs[pos] = __ldg(src + e);
}

// ---------------------------------------------------------------------------
// atomic-free mean aggregation: fp16 in, fp32 accumulate, fp16 out
// ---------------------------------------------------------------------------
__global__ __launch_bounds__(256) void aggregate_h(
    const __half* __restrict__ feat16,
    const int*    __restrict__ rowptr,
    const int*    __restrict__ srcs,
    __half*       __restrict__ aggh)
{
    const int node = blockIdx.x * 8 + (threadIdx.x >> 5);
    const int lane = threadIdx.x & 31;
    if (node >= NN) return;

    const int beg = __ldg(rowptr + node);
    const int end = __ldg(rowptr + node + 1);

    const uint2* fb = (const uint2*)feat16 + lane;   // row = 32 uint2

    float a0 = 0.f, a1 = 0.f, a2 = 0.f, a3 = 0.f;
    int e = beg;
    for (; e + 4 <= end; e += 4) {
        int s0 = __ldg(srcs + e);
        int s1 = __ldg(srcs + e + 1);
        int s2 = __ldg(srcs + e + 2);
        int s3 = __ldg(srcs + e + 3);
        uint2 u0 = __ldg(fb + (size_t)s0 * 32);
        uint2 u1 = __ldg(fb + (size_t)s1 * 32);
        uint2 u2 = __ldg(fb + (size_t)s2 * 32);
        uint2 u3 = __ldg(fb + (size_t)s3 * 32);
#pragma unroll
        for (int j = 0; j < 4; j++) {
            uint2 u = (j == 0) ? u0 : (j == 1) ? u1 : (j == 2) ? u2 : u3;
            float2 f0 = __half22float2(*(__half2*)&u.x);
            float2 f1 = __half22float2(*(__half2*)&u.y);
            a0 += f0.x; a1 += f0.y; a2 += f1.x; a3 += f1.y;
        }
    }
    for (; e < end; e++) {
        int s0 = __ldg(srcs + e);
        uint2 u = __ldg(fb + (size_t)s0 * 32);
        float2 f0 = __half22float2(*(__half2*)&u.x);
        float2 f1 = __half22float2(*(__half2*)&u.y);
        a0 += f0.x; a1 += f0.y; a2 += f1.x; a3 += f1.y;
    }

    const int deg = end - beg;
    const float inv = 1.f / (float)(deg > 1 ? deg : 1);
    __half2 o0 = __floats2half2_rn(a0 * inv, a1 * inv);
    __half2 o1 = __floats2half2_rn(a2 * inv, a3 * inv);
    *((uint2*)(aggh + (size_t)node * C) + lane) =
        make_uint2(*(uint32_t*)&o0, *(uint32_t*)&o1);
}

// ---------------------------------------------------------------------------
// fp16 HMMA fused dual-matmul layer:
//   acc = A1·W{s0}^T + A2·W{s1}^T ; out = relu(acc + bias)
// 2 passes, each one full K=128 tile (A 128x128 fp16 + W 128x128 fp16 in smem).
// 256 thr, warp tile 32x64, m16n8k16 f16 mma via ldmatrix.x4. 2 CTAs/SM.
// ---------------------------------------------------------------------------
#define PITCH  136
#define SLAB_B (128 * PITCH * 2)        // 34816
#define A_OFF  0
#define W_OFF  SLAB_B
#define SMEM_BYTES (2 * SLAB_B)         // 69632

__global__ __launch_bounds__(256, 2) void hmma_layer(
    const __half* __restrict__ A1, const __half* __restrict__ A2,
    const __half* __restrict__ wh, int s0, int s1,
    const float* __restrict__ bias,
    float* __restrict__ out32, __half* __restrict__ outh,
    int nrows)
{
    extern __shared__ char sm[];
    const uint32_t smb = smem_u32(sm);
    const int t = threadIdx.x, wid = t >> 5, lane = t & 31;
    const int nb = blockIdx.x * 128;

    const int mBase = (wid & 3) * 32;
    const int nBase = (wid >> 2) * 64;

    const int arow = (lane & 7) + ((lane >> 3) & 1) * 8;
    const int acol = (lane >> 4) * 8;
    const int brow = (lane & 7) + (lane >> 4) * 8;
    const int bcol = ((lane >> 3) & 1) * 8;
    const uint32_t aoff0 = ((mBase + arow) * PITCH + acol) * 2;
    const uint32_t aoff1 = aoff0 + 16 * PITCH * 2;
    const uint32_t boff  = ((nBase + brow) * PITCH + bcol) * 2;

    float acc[2][8][4];
#pragma unroll
    for (int mt = 0; mt < 2; mt++)
#pragma unroll
        for (int nt = 0; nt < 8; nt++)
#pragma unroll
            for (int j = 0; j < 4; j++) acc[mt][nt][j] = 0.f;

#pragma unroll 1
    for (int pass = 0; pass < 2; pass++) {
        const __half* A = pass ? A2 : A1;
        const __half* W = wh + (size_t)(pass ? s1 : s0) * 16384;

        // -- stage A (128x128 fp16) + W (128x128 fp16) via cp.async --
        for (int i = t; i < 2048; i += 256) {
            const int r   = i >> 4;
            const int seg = i & 15;
            cp16(smb + A_OFF + r * (PITCH * 2) + seg * 16,
                 A + (size_t)(nb + r) * C + seg * 8);
        }
        for (int i = t; i < 2048; i += 256) {
            const int r   = i >> 4;
            const int seg = i & 15;
            cp16(smb + W_OFF + r * (PITCH * 2) + seg * 16,
                 W + (size_t)r * 128 + seg * 8);
        }
        asm volatile("cp.async.commit_group;" ::: "memory");
        asm volatile("cp.async.wait_group 0;" ::: "memory");
        __syncthreads();

        // -- MMA: 8 k16 steps --
#pragma unroll
        for (int ks = 0; ks < 8; ks++) {
            uint32_t a0[4], a1[4];
            ldsm4(smb + A_OFF + aoff0 + ks * 32, a0);
            ldsm4(smb + A_OFF + aoff1 + ks * 32, a1);
#pragma unroll
            for (int p = 0; p < 4; p++) {
                uint32_t b[4];
                ldsm4(smb + W_OFF + boff + p * (16 * PITCH * 2) + ks * 32, b);
                mma16816h(acc[0][2 * p],     a0, b);
                mma16816h(acc[1][2 * p],     a1, b);
                mma16816h(acc[0][2 * p + 1], a0, b + 2);
                mma16816h(acc[1][2 * p + 1], a1, b + 2);
            }
        }
        __syncthreads();
    }

    // -- epilogue: bias + relu --
    const int qrow = lane >> 2;
    const int qk   = (lane & 3) * 2;
#pragma unroll
    for (int nt = 0; nt < 8; nt++) {
        const int cl = nBase + nt * 8 + qk;
        const float2 b = __ldg((const float2*)(bias + cl));
#pragma unroll
        for (int mt = 0; mt < 2; mt++) {
#pragma unroll
            for (int half = 0; half < 2; half++) {
                const int r = nb + mBase + mt * 16 + qrow + half * 8;
                if (r < nrows) {
                    float ox = fmaxf(acc[mt][nt][2 * half]     + b.x, 0.f);
                    float oy = fmaxf(acc[mt][nt][2 * half + 1] + b.y, 0.f);
                    const size_t off = (size_t)r * C + cl;
                    if (out32) *(float2*)(out32 + off) = make_float2(ox, oy);
                    if (outh) {
                        __half2 hh = __floats2half2_rn(ox, oy);
                        *(__half2*)(outh + off) = hh;
                    }
                }
            }
        }
    }
}

// ---------------------------------------------------------------------------
// launch
// ---------------------------------------------------------------------------
extern "C" void kernel_launch(void* const* d_in, const int* in_sizes, int n_in,
                              void* d_out, int out_size)
{
    const float* x    = (const float*)d_in[0];
    const int*   ei   = (const int*)  d_in[1];
    const float* Wl1  = (const float*)d_in[2];
    const float* Wr1  = (const float*)d_in[3];
    const float* b1   = (const float*)d_in[4];
    const float* Wl2  = (const float*)d_in[5];
    const float* Wr2  = (const float*)d_in[6];
    const float* b2   = (const float*)d_in[7];
    const float* Wlin = (const float*)d_in[8];
    const float* blin = (const float*)d_in[9];
    float*       out  = (float*)d_out;

    const int* src = ei;
    const int* dst = ei + EE;

    void *xh_v, *aggh_v, *h1h_v, *h2h_v, *wh_v;
    void *cnt_v, *rp_v, *cur_v, *part_v, *srcs_v;
    cudaGetSymbolAddress(&xh_v,   g_xh);
    cudaGetSymbolAddress(&aggh_v, g_aggh);
    cudaGetSymbolAddress(&h1h_v,  g_h1h);
    cudaGetSymbolAddress(&h2h_v,  g_h2h);
    cudaGetSymbolAddress(&wh_v,   g_wh);
    cudaGetSymbolAddress(&cnt_v,  g_cnt);
    cudaGetSymbolAddress(&rp_v,   g_rowptr);
    cudaGetSymbolAddress(&cur_v,  g_cursor);
    cudaGetSymbolAddress(&part_v, g_part);
    cudaGetSymbolAddress(&srcs_v, g_srcs);
    __half* xh   = (__half*)xh_v;
    __half* aggh = (__half*)aggh_v;
    __half* h1h  = (__half*)h1h_v;
    __half* h2h  = (__half*)h2h_v;
    __half* wh   = (__half*)wh_v;
    int* cnt    = (int*)cnt_v;
    int* rowptr = (int*)rp_v;
    int* cursor = (int*)cur_v;
    int* part   = (int*)part_v;
    int* srcs   = (int*)srcs_v;

    cudaFuncSetAttribute(hmma_layer,
                         cudaFuncAttributeMaxDynamicSharedMemorySize, SMEM_BYTES);

    const int eblk = (EE + 255) / 256;          // 6250
    const int gblk = (NN + 127) / 128;          // 782
    const int ablk = (NN + 7) / 8;              // 12500
    const int wblk = (6 * 16384 + 255) / 256;
    const int n4   = NN * C / 4;                // 3,200,000
    const int fblk = (n4 + 255) / 256;

    // ---- prep: fp16 weights + fp16 x table + CSR build ----
    weights_h<<<wblk, 256>>>(Wl1, Wr1, Wl2, Wr2, Wlin, wh);
    to_half_feat<<<fblk, 256>>>(x, xh, n4);
    zero_i<<<(NN + 255) / 256, 256>>>(cnt, NN);
    hist_kernel<<<eblk, 256>>>(dst, cnt);
    scan_blk<<<NB, 1024>>>(cnt, rowptr, part);
    scan_part<<<1, 128>>>(part);
    scan_add<<<NB, 1024>>>(part, rowptr, cursor);
    scatter_csr<<<eblk, 256>>>(src, dst, cursor, srcs);

    // ---- conv1: gather(x) -> aggh; h1 = relu(aggh·Wl1 + x·Wr1 + b1) ----
    aggregate_h<<<ablk, 256>>>(xh, rowptr, srcs, aggh);
    hmma_layer<<<gblk, 256, SMEM_BYTES>>>(aggh, xh, wh, 0, 1, b1, nullptr, h1h, NN);

    // ---- conv2: gather(h1) -> aggh; h2 = relu(aggh·Wl2 + h1·Wr2 + b2) ----
    aggregate_h<<<ablk, 256>>>(h1h, rowptr, srcs, aggh);
    hmma_layer<<<gblk, 256, SMEM_BYTES>>>(aggh, h1h, wh, 2, 3, b2, nullptr, h2h, NN);

    // ---- JK-cat + linear head: out = relu(h1·Wlin[:,:128] + h2·Wlin[:,128:] + blin) ----
    hmma_layer<<<gblk, 256, SMEM_BYTES>>>(h1h, h2h, wh, 4, 5, blin, out, nullptr, NN);
}

// round 13
// speedup vs baseline: 1.5805x; 1.0092x over previous
#include <cuda_runtime.h>
#include <cuda_fp16.h>
#include <cstdint>
#include <cstddef>

#define NN 100000
#define EE 1600000
#define C  128
#define NB 98                 // scan blocks: ceil(100000/1024)
#define NP (NN + 128)         // padded rows: edge-tile cp.async stays in-bounds

// ---- scratch (device globals: allocation-free) ----
__device__ __half g_xh  [(size_t)NP * C];
__device__ __half g_aggh[(size_t)NP * C];
__device__ __half g_h1h [(size_t)NP * C];
__device__ __half g_h2h [(size_t)NP * C];
__device__ __half g_wh[6 * 16384];
__device__ int g_cnt[NN];
__device__ int g_rowptr[NN + 1];
__device__ int g_cursor[NN];
__device__ int g_part[NB];
__device__ int g_srcs[EE];

// ---------------------------------------------------------------------------
// helpers
// ---------------------------------------------------------------------------
__device__ __forceinline__ uint32_t smem_u32(const void* p) {
    uint32_t a;
    asm("{ .reg .u64 t; cvta.to.shared.u64 t, %1; cvt.u32.u64 %0, t; }"
        : "=r"(a) : "l"(p));
    return a;
}
__device__ __forceinline__ void cp16(uint32_t saddr, const void* g) {
    asm volatile("cp.async.cg.shared.global [%0], [%1], 16;"
                 :: "r"(saddr), "l"(g) : "memory");
}
__device__ __forceinline__ void ldsm4(uint32_t addr, uint32_t* r) {
    asm volatile("ldmatrix.sync.aligned.m8n8.x4.shared.b16 {%0,%1,%2,%3}, [%4];"
                 : "=r"(r[0]), "=r"(r[1]), "=r"(r[2]), "=r"(r[3]) : "r"(addr));
}
__device__ __forceinline__ void mma16816h(float* c, const uint32_t* a, const uint32_t* b) {
    asm volatile(
        "mma.sync.aligned.m16n8k16.row.col.f32.f16.f16.f32 "
        "{%0,%1,%2,%3}, {%4,%5,%6,%7}, {%8,%9}, {%0,%1,%2,%3};"
        : "+f"(c[0]), "+f"(c[1]), "+f"(c[2]), "+f"(c[3])
        : "r"(a[0]), "r"(a[1]), "r"(a[2]), "r"(a[3]), "r"(b[0]), "r"(b[1]));
}
__device__ __forceinline__ int warp_iscan(int v, int lane) {
#pragma unroll
    for (int d = 1; d < 32; d <<= 1) {
        int n = __shfl_up_sync(0xFFFFFFFFu, v, d);
        if (lane >= d) v += n;
    }
    return v;
}

// ---------------------------------------------------------------------------
// fused prep: x->fp16 table | weights->fp16 | zero cnt  (one launch)
// ---------------------------------------------------------------------------
#define N4    (NN * C / 4)                 // 3,200,000 float4 groups
#define WTOT  (6 * 16384)                  // 98,304 weight elems
#define PREP_TOT (N4 + WTOT + NN)

__global__ void prep_all(const float* __restrict__ x,
                         const float* __restrict__ Wl1, const float* __restrict__ Wr1,
                         const float* __restrict__ Wl2, const float* __restrict__ Wr2,
                         const float* __restrict__ Wlin,
                         __half* __restrict__ xh, __half* __restrict__ wh,
                         int* __restrict__ cnt)
{
    int i = blockIdx.x * blockDim.x + threadIdx.x;
    if (i < N4) {
        float4 v = __ldg((const float4*)x + i);
        __half2 h0 = __floats2half2_rn(v.x, v.y);
        __half2 h1 = __floats2half2_rn(v.z, v.w);
        *(uint2*)(xh + (size_t)i * 4) = make_uint2(*(uint32_t*)&h0, *(uint32_t*)&h1);
    } else if (i < N4 + WTOT) {
        int j = i - N4;
        int s = j >> 14, r = (j >> 7) & 127, k = j & 127;
        float v;
        switch (s) {
            case 0:  v = __ldg(Wl1 + r * 128 + k); break;
            case 1:  v = __ldg(Wr1 + r * 128 + k); break;
            case 2:  v = __ldg(Wl2 + r * 128 + k); break;
            case 3:  v = __ldg(Wr2 + r * 128 + k); break;
            case 4:  v = __ldg(Wlin + r * 256 + k); break;
            default: v = __ldg(Wlin + r * 256 + 128 + k); break;
        }
        wh[j] = __float2half_rn(v);
    } else if (i < PREP_TOT) {
        cnt[i - N4 - WTOT] = 0;
    }
}

// ---------------------------------------------------------------------------
// CSR build: histogram -> 3-phase scan -> bucket scatter
// ---------------------------------------------------------------------------
__global__ void hist_kernel(const int* __restrict__ dst, int* __restrict__ cnt) {
    int e = blockIdx.x * blockDim.x + threadIdx.x;
    if (e < EE) atomicAdd(cnt + __ldg(dst + e), 1);
}

__global__ __launch_bounds__(1024) void scan_blk(
    const int* __restrict__ cnt, int* __restrict__ rowptr, int* __restrict__ part)
{
    __shared__ int ws[32];
    const int t = threadIdx.x, lane = t & 31, w = t >> 5;
    const int i = blockIdx.x * 1024 + t;
    const int v = (i < NN) ? __ldg(cnt + i) : 0;

    int x = warp_iscan(v, lane);
    if (lane == 31) ws[w] = x;
    __syncthreads();
    if (w == 0) ws[lane] = warp_iscan(ws[lane], lane);
    __syncthreads();

    const int incl = x + (w ? ws[w - 1] : 0);
    if (i < NN) rowptr[i] = incl - v;
    if (t == 1023) part[blockIdx.x] = incl;
}

__global__ __launch_bounds__(128) void scan_part(int* __restrict__ part) {
    __shared__ int ws[4];
    const int t = threadIdx.x, lane = t & 31, w = t >> 5;
    const int v = (t < NB) ? part[t] : 0;
    int x = warp_iscan(v, lane);
    if (lane == 31) ws[w] = x;
    __syncthreads();
    if (t == 0) {
        int run = 0;
        for (int j = 0; j < 4; j++) { int s = ws[j]; ws[j] = run; run += s; }
    }
    __syncthreads();
    if (t < NB) part[t] = x - v + ws[w];
}

__global__ __launch_bounds__(1024) void scan_add(
    const int* __restrict__ part, int* __restrict__ rowptr, int* __restrict__ cursor)
{
    const int i = blockIdx.x * 1024 + threadIdx.x;
    if (i < NN) {
        int r = rowptr[i] + part[blockIdx.x];
        rowptr[i] = r;
        cursor[i] = r;
    }
    if (i == 0) rowptr[NN] = EE;
}

__global__ void scatter_csr(const int* __restrict__ src, const int* __restrict__ dst,
                            int* __restrict__ cursor, int* __restrict__ srcs)
{
    int e = blockIdx.x * blockDim.x + threadIdx.x;
    if (e >= EE) return;
    int d = __ldg(dst + e);
    int pos = atomicAdd(cursor + d, 1);
    srcs[pos] = __ldg(src + e);
}

// ---------------------------------------------------------------------------
// atomic-free mean aggregation: fp16 in, fp32 accumulate, fp16 out; unroll 8
// ---------------------------------------------------------------------------
__global__ __launch_bounds__(256) void aggregate_h(
    const __half* __restrict__ feat16,
    const int*    __restrict__ rowptr,
    const int*    __restrict__ srcs,
    __half*       __restrict__ aggh)
{
    const int node = blockIdx.x * 8 + (threadIdx.x >> 5);
    const int lane = threadIdx.x & 31;
    if (node >= NN) return;

    const int beg = __ldg(rowptr + node);
    const int end = __ldg(rowptr + node + 1);

    const uint2* fb = (const uint2*)feat16 + lane;   // row = 32 uint2

    float a0 = 0.f, a1 = 0.f, a2 = 0.f, a3 = 0.f;
    int e = beg;
    for (; e + 8 <= end; e += 8) {
        int s[8];
#pragma unroll
        for (int j = 0; j < 8; j++) s[j] = __ldg(srcs + e + j);
        uint2 u[8];
#pragma unroll
        for (int j = 0; j < 8; j++) u[j] = __ldg(fb + (size_t)s[j] * 32);
#pragma unroll
        for (int j = 0; j < 8; j++) {
            float2 f0 = __half22float2(*(__half2*)&u[j].x);
            float2 f1 = __half22float2(*(__half2*)&u[j].y);
            a0 += f0.x; a1 += f0.y; a2 += f1.x; a3 += f1.y;
        }
    }
    for (; e < end; e++) {
        int s0 = __ldg(srcs + e);
        uint2 u = __ldg(fb + (size_t)s0 * 32);
        float2 f0 = __half22float2(*(__half2*)&u.x);
        float2 f1 = __half22float2(*(__half2*)&u.y);
        a0 += f0.x; a1 += f0.y; a2 += f1.x; a3 += f1.y;
    }

    const int deg = end - beg;
    const float inv = 1.f / (float)(deg > 1 ? deg : 1);
    __half2 o0 = __floats2half2_rn(a0 * inv, a1 * inv);
    __half2 o1 = __floats2half2_rn(a2 * inv, a3 * inv);
    *((uint2*)(aggh + (size_t)node * C) + lane) =
        make_uint2(*(uint32_t*)&o0, *(uint32_t*)&o1);
}

// ---------------------------------------------------------------------------
// fp16 HMMA fused dual-matmul layer (round-11 version, known good):
//   acc = A1·W{s0}^T + A2·W{s1}^T ; out = relu(acc + bias)
// 2 passes, each one full K=128 tile (A 128x128 fp16 + W 128x128 fp16 in smem).
// 256 thr, warp tile 32x64, m16n8k16 f16 mma via ldmatrix.x4. 2 CTAs/SM.
// ---------------------------------------------------------------------------
#define PITCH  136
#define SLAB_B (128 * PITCH * 2)        // 34816
#define A_OFF  0
#define W_OFF  SLAB_B
#define SMEM_BYTES (2 * SLAB_B)         // 69632

__global__ __launch_bounds__(256, 2) void hmma_layer(
    const __half* __restrict__ A1, const __half* __restrict__ A2,
    const __half* __restrict__ wh, int s0, int s1,
    const float* __restrict__ bias,
    float* __restrict__ out32, __half* __restrict__ outh,
    int nrows)
{
    extern __shared__ char sm[];
    const uint32_t smb = smem_u32(sm);
    const int t = threadIdx.x, wid = t >> 5, lane = t & 31;
    const int nb = blockIdx.x * 128;

    const int mBase = (wid & 3) * 32;
    const int nBase = (wid >> 2) * 64;

    const int arow = (lane & 7) + ((lane >> 3) & 1) * 8;
    const int acol = (lane >> 4) * 8;
    const int brow = (lane & 7) + (lane >> 4) * 8;
    const int bcol = ((lane >> 3) & 1) * 8;
    const uint32_t aoff0 = ((mBase + arow) * PITCH + acol) * 2;
    const uint32_t aoff1 = aoff0 + 16 * PITCH * 2;
    const uint32_t boff  = ((nBase + brow) * PITCH + bcol) * 2;

    float acc[2][8][4];
#pragma unroll
    for (int mt = 0; mt < 2; mt++)
#pragma unroll
        for (int nt = 0; nt < 8; nt++)
#pragma unroll
            for (int j = 0; j < 4; j++) acc[mt][nt][j] = 0.f;

#pragma unroll 1
    for (int pass = 0; pass < 2; pass++) {
        const __half* A = pass ? A2 : A1;
        const __half* W = wh + (size_t)(pass ? s1 : s0) * 16384;

        // -- stage A (128x128 fp16) + W (128x128 fp16) via cp.async --
        for (int i = t; i < 2048; i += 256) {
            const int r   = i >> 4;
            const int seg = i & 15;
            cp16(smb + A_OFF + r * (PITCH * 2) + seg * 16,
                 A + (size_t)(nb + r) * C + seg * 8);
        }
        for (int i = t; i < 2048; i += 256) {
            const int r   = i >> 4;
            const int seg = i & 15;
            cp16(smb + W_OFF + r * (PITCH * 2) + seg * 16,
                 W + (size_t)r * 128 + seg * 8);
        }
        asm volatile("cp.async.commit_group;" ::: "memory");
        asm volatile("cp.async.wait_group 0;" ::: "memory");
        __syncthreads();

        // -- MMA: 8 k16 steps --
#pragma unroll
        for (int ks = 0; ks < 8; ks++) {
            uint32_t a0[4], a1[4];
            ldsm4(smb + A_OFF + aoff0 + ks * 32, a0);
            ldsm4(smb + A_OFF + aoff1 + ks * 32, a1);
#pragma unroll
            for (int p = 0; p < 4; p++) {
                uint32_t b[4];
                ldsm4(smb + W_OFF + boff + p * (16 * PITCH * 2) + ks * 32, b);
                mma16816h(acc[0][2 * p],     a0, b);
                mma16816h(acc[1][2 * p],     a1, b);
                mma16816h(acc[0][2 * p + 1], a0, b + 2);
                mma16816h(acc[1][2 * p + 1], a1, b + 2);
            }
        }
        __syncthreads();
    }

    // -- epilogue: bias + relu --
    const int qrow = lane >> 2;
    const int qk   = (lane & 3) * 2;
#pragma unroll
    for (int nt = 0; nt < 8; nt++) {
        const int cl = nBase + nt * 8 + qk;
        const float2 b = __ldg((const float2*)(bias + cl));
#pragma unroll
        for (int mt = 0; mt < 2; mt++) {
#pragma unroll
            for (int half = 0; half < 2; half++) {
                const int r = nb + mBase + mt * 16 + qrow + half * 8;
                if (r < nrows) {
                    float ox = fmaxf(acc[mt][nt][2 * half]     + b.x, 0.f);
                    float oy = fmaxf(acc[mt][nt][2 * half + 1] + b.y, 0.f);
                    const size_t off = (size_t)r * C + cl;
                    if (out32) *(float2*)(out32 + off) = make_float2(ox, oy);
                    if (outh) {
                        __half2 hh = __floats2half2_rn(ox, oy);
                        *(__half2*)(outh + off) = hh;
                    }
                }
            }
        }
    }
}

// ---------------------------------------------------------------------------
// launch
// ---------------------------------------------------------------------------
extern "C" void kernel_launch(void* const* d_in, const int* in_sizes, int n_in,
                              void* d_out, int out_size)
{
    const float* x    = (const float*)d_in[0];
    const int*   ei   = (const int*)  d_in[1];
    const float* Wl1  = (const float*)d_in[2];
    const float* Wr1  = (const float*)d_in[3];
    const float* b1   = (const float*)d_in[4];
    const float* Wl2  = (const float*)d_in[5];
    const float* Wr2  = (const float*)d_in[6];
    const float* b2   = (const float*)d_in[7];
    const float* Wlin = (const float*)d_in[8];
    const float* blin = (const float*)d_in[9];
    float*       out  = (float*)d_out;

    const int* src = ei;
    const int* dst = ei + EE;

    void *xh_v, *aggh_v, *h1h_v, *h2h_v, *wh_v;
    void *cnt_v, *rp_v, *cur_v, *part_v, *srcs_v;
    cudaGetSymbolAddress(&xh_v,   g_xh);
    cudaGetSymbolAddress(&aggh_v, g_aggh);
    cudaGetSymbolAddress(&h1h_v,  g_h1h);
    cudaGetSymbolAddress(&h2h_v,  g_h2h);
    cudaGetSymbolAddress(&wh_v,   g_wh);
    cudaGetSymbolAddress(&cnt_v,  g_cnt);
    cudaGetSymbolAddress(&rp_v,   g_rowptr);
    cudaGetSymbolAddress(&cur_v,  g_cursor);
    cudaGetSymbolAddress(&part_v, g_part);
    cudaGetSymbolAddress(&srcs_v, g_srcs);
    __half* xh   = (__half*)xh_v;
    __half* aggh = (__half*)aggh_v;
    __half* h1h  = (__half*)h1h_v;
    __half* h2h  = (__half*)h2h_v;
    __half* wh   = (__half*)wh_v;
    int* cnt    = (int*)cnt_v;
    int* rowptr = (int*)rp_v;
    int* cursor = (int*)cur_v;
    int* part   = (int*)part_v;
    int* srcs   = (int*)srcs_v;

    cudaFuncSetAttribute(hmma_layer,
                         cudaFuncAttributeMaxDynamicSharedMemorySize, SMEM_BYTES);

    const int eblk = (EE + 255) / 256;           // 6250
    const int gblk = (NN + 127) / 128;           // 782
    const int ablk = (NN + 7) / 8;               // 12500
    const int pblk = (PREP_TOT + 255) / 256;

    // ---- prep (one kernel) + CSR build ----
    prep_all<<<pblk, 256>>>(x, Wl1, Wr1, Wl2, Wr2, Wlin, xh, wh, cnt);
    hist_kernel<<<eblk, 256>>>(dst, cnt);
    scan_blk<<<NB, 1024>>>(cnt, rowptr, part);
    scan_part<<<1, 128>>>(part);
    scan_add<<<NB, 1024>>>(part, rowptr, cursor);
    scatter_csr<<<eblk, 256>>>(src, dst, cursor, srcs);

    // ---- conv1: gather(x) -> aggh; h1 = relu(aggh·Wl1 + x·Wr1 + b1) ----
    aggregate_h<<<ablk, 256>>>(xh, rowptr, srcs, aggh);
    hmma_layer<<<gblk, 256, SMEM_BYTES>>>(aggh, xh, wh, 0, 1, b1, nullptr, h1h, NN);

    // ---- conv2: gather(h1) -> aggh; h2 = relu(aggh·Wl2 + h1·Wr2 + b2) ----
    aggregate_h<<<ablk, 256>>>(h1h, rowptr, srcs, aggh);
    hmma_layer<<<gblk, 256, SMEM_BYTES>>>(aggh, h1h, wh, 2, 3, b2, nullptr, h2h, NN);

    // ---- JK-cat + linear head ----
    hmma_layer<<<gblk, 256, SMEM_BYTES>>>(h1h, h2h, wh, 4, 5, blin, out, nullptr, NN);
}

// round 14
// speedup vs baseline: 1.6458x; 1.0413x over previous
#include <cuda_runtime.h>
#include <cuda_fp16.h>
#include <cstdint>
#include <cstddef>

#define NN 100000
#define EE 1600000
#define C  128
#define NB 98                 // scan blocks: ceil(100000/1024)
#define NP (NN + 128)         // padded rows: edge-tile cp.async stays in-bounds

// ---- scratch (device globals: allocation-free) ----
__device__ __half g_xh  [(size_t)NP * C];
__device__ __half g_aggh[(size_t)NP * C];
__device__ __half g_h1h [(size_t)NP * C];
__device__ __half g_h2h [(size_t)NP * C];
__device__ __half g_wh[6 * 16384];
__device__ int g_cnt[NN];
__device__ int g_rowptr[NN + 1];
__device__ int g_cursor[NN];
__device__ int g_part[NB];
__device__ int g_srcs[EE];

// ---------------------------------------------------------------------------
// helpers
// ---------------------------------------------------------------------------
__device__ __forceinline__ uint32_t smem_u32(const void* p) {
    uint32_t a;
    asm("{ .reg .u64 t; cvta.to.shared.u64 t, %1; cvt.u32.u64 %0, t; }"
        : "=r"(a) : "l"(p));
    return a;
}
__device__ __forceinline__ void cp16(uint32_t saddr, const void* g) {
    asm volatile("cp.async.cg.shared.global [%0], [%1], 16;"
                 :: "r"(saddr), "l"(g) : "memory");
}
__device__ __forceinline__ void ldsm4(uint32_t addr, uint32_t* r) {
    asm volatile("ldmatrix.sync.aligned.m8n8.x4.shared.b16 {%0,%1,%2,%3}, [%4];"
                 : "=r"(r[0]), "=r"(r[1]), "=r"(r[2]), "=r"(r[3]) : "r"(addr));
}
__device__ __forceinline__ void mma16816h(float* c, const uint32_t* a, const uint32_t* b) {
    asm volatile(
        "mma.sync.aligned.m16n8k16.row.col.f32.f16.f16.f32 "
        "{%0,%1,%2,%3}, {%4,%5,%6,%7}, {%8,%9}, {%0,%1,%2,%3};"
        : "+f"(c[0]), "+f"(c[1]), "+f"(c[2]), "+f"(c[3])
        : "r"(a[0]), "r"(a[1]), "r"(a[2]), "r"(a[3]), "r"(b[0]), "r"(b[1]));
}
__device__ __forceinline__ int warp_iscan(int v, int lane) {
#pragma unroll
    for (int d = 1; d < 32; d <<= 1) {
        int n = __shfl_up_sync(0xFFFFFFFFu, v, d);
        if (lane >= d) v += n;
    }
    return v;
}

// ---------------------------------------------------------------------------
// fused prep: x->fp16 table | weights->fp16 | zero cnt  (one launch)
// ---------------------------------------------------------------------------
#define N4    (NN * C / 4)                 // 3,200,000 float4 groups
#define WTOT  (6 * 16384)                  // 98,304 weight elems
#define PREP_TOT (N4 + WTOT + NN)

__global__ void prep_all(const float* __restrict__ x,
                         const float* __restrict__ Wl1, const float* __restrict__ Wr1,
                         const float* __restrict__ Wl2, const float* __restrict__ Wr2,
                         const float* __restrict__ Wlin,
                         __half* __restrict__ xh, __half* __restrict__ wh,
                         int* __restrict__ cnt)
{
    int i = blockIdx.x * blockDim.x + threadIdx.x;
    if (i < N4) {
        float4 v = __ldg((const float4*)x + i);
        __half2 h0 = __floats2half2_rn(v.x, v.y);
        __half2 h1 = __floats2half2_rn(v.z, v.w);
        *(uint2*)(xh + (size_t)i * 4) = make_uint2(*(uint32_t*)&h0, *(uint32_t*)&h1);
    } else if (i < N4 + WTOT) {
        int j = i - N4;
        int s = j >> 14, r = (j >> 7) & 127, k = j & 127;
        float v;
        switch (s) {
            case 0:  v = __ldg(Wl1 + r * 128 + k); break;
            case 1:  v = __ldg(Wr1 + r * 128 + k); break;
            case 2:  v = __ldg(Wl2 + r * 128 + k); break;
            case 3:  v = __ldg(Wr2 + r * 128 + k); break;
            case 4:  v = __ldg(Wlin + r * 256 + k); break;
            default: v = __ldg(Wlin + r * 256 + 128 + k); break;
        }
        wh[j] = __float2half_rn(v);
    } else if (i < PREP_TOT) {
        cnt[i - N4 - WTOT] = 0;
    }
}

// ---------------------------------------------------------------------------
// CSR build: histogram -> block scan -> (fused partial-scan + add) -> scatter
// ---------------------------------------------------------------------------
__global__ void hist_kernel(const int* __restrict__ dst, int* __restrict__ cnt) {
    int e = blockIdx.x * blockDim.x + threadIdx.x;
    if (e < EE) atomicAdd(cnt + __ldg(dst + e), 1);
}

__global__ __launch_bounds__(1024) void scan_blk(
    const int* __restrict__ cnt, int* __restrict__ rowptr, int* __restrict__ part)
{
    __shared__ int ws[32];
    const int t = threadIdx.x, lane = t & 31, w = t >> 5;
    const int i = blockIdx.x * 1024 + t;
    const int v = (i < NN) ? __ldg(cnt + i) : 0;

    int x = warp_iscan(v, lane);
    if (lane == 31) ws[w] = x;
    __syncthreads();
    if (w == 0) ws[lane] = warp_iscan(ws[lane], lane);
    __syncthreads();

    const int incl = x + (w ? ws[w - 1] : 0);
    if (i < NN) rowptr[i] = incl - v;
    if (t == 1023) part[blockIdx.x] = incl;
}

// fused: every block computes the exclusive scan of the 98 partials locally,
// then adds its own offset. Removes the scan_part launch.
__global__ __launch_bounds__(1024) void scan_add2(
    const int* __restrict__ part, int* __restrict__ rowptr, int* __restrict__ cursor)
{
    __shared__ int sp[128];
    __shared__ int wt[4];
    const int t = threadIdx.x;
    if (t < 128) {
        const int lane = t & 31, w = t >> 5;
        const int v = (t < NB) ? __ldg(part + t) : 0;
        int x = warp_iscan(v, lane);
        sp[t] = x - v;                  // exclusive within warp
        if (lane == 31) wt[w] = x;      // warp total
    }
    __syncthreads();
    if (t < 128) {
        const int w = t >> 5;
        int add = 0;
        for (int j = 0; j < w; j++) add += wt[j];
        sp[t] += add;                   // global exclusive prefix of partials
    }
    __syncthreads();

    const int i = blockIdx.x * 1024 + t;
    if (i < NN) {
        const int r = rowptr[i] + sp[blockIdx.x];
        rowptr[i] = r;
        cursor[i] = r;
    }
    if (i == 0) rowptr[NN] = EE;
}

__global__ void scatter_csr(const int* __restrict__ src, const int* __restrict__ dst,
                            int* __restrict__ cursor, int* __restrict__ srcs)
{
    int e = blockIdx.x * blockDim.x + threadIdx.x;
    if (e >= EE) return;
    int d = __ldg(dst + e);
    int pos = atomicAdd(cursor + d, 1);
    srcs[pos] = __ldg(src + e);
}

// ---------------------------------------------------------------------------
// atomic-free mean aggregation: fp16 in, fp32 accumulate, fp16 out; unroll 8
// ---------------------------------------------------------------------------
__global__ __launch_bounds__(256) void aggregate_h(
    const __half* __restrict__ feat16,
    const int*    __restrict__ rowptr,
    const int*    __restrict__ srcs,
    __half*       __restrict__ aggh)
{
    const int node = blockIdx.x * 8 + (threadIdx.x >> 5);
    const int lane = threadIdx.x & 31;
    if (node >= NN) return;

    const int beg = __ldg(rowptr + node);
    const int end = __ldg(rowptr + node + 1);

    const uint2* fb = (const uint2*)feat16 + lane;   // row = 32 uint2

    float a0 = 0.f, a1 = 0.f, a2 = 0.f, a3 = 0.f;
    int e = beg;
    for (; e + 8 <= end; e += 8) {
        int s[8];
#pragma unroll
        for (int j = 0; j < 8; j++) s[j] = __ldg(srcs + e + j);
        uint2 u[8];
#pragma unroll
        for (int j = 0; j < 8; j++) u[j] = __ldg(fb + (size_t)s[j] * 32);
#pragma unroll
        for (int j = 0; j < 8; j++) {
            float2 f0 = __half22float2(*(__half2*)&u[j].x);
            float2 f1 = __half22float2(*(__half2*)&u[j].y);
            a0 += f0.x; a1 += f0.y; a2 += f1.x; a3 += f1.y;
        }
    }
    for (; e < end; e++) {
        int s0 = __ldg(srcs + e);
        uint2 u = __ldg(fb + (size_t)s0 * 32);
        float2 f0 = __half22float2(*(__half2*)&u.x);
        float2 f1 = __half22float2(*(__half2*)&u.y);
        a0 += f0.x; a1 += f0.y; a2 += f1.x; a3 += f1.y;
    }

    const int deg = end - beg;
    const float inv = 1.f / (float)(deg > 1 ? deg : 1);
    __half2 o0 = __floats2half2_rn(a0 * inv, a1 * inv);
    __half2 o1 = __floats2half2_rn(a2 * inv, a3 * inv);
    *((uint2*)(aggh + (size_t)node * C) + lane) =
        make_uint2(*(uint32_t*)&o0, *(uint32_t*)&o1);
}

// ---------------------------------------------------------------------------
// fp16 HMMA fused dual-matmul layer, software-pipelined (flat, no lambdas):
//   acc = A1·W{s0}^T + A2·W{s1}^T ; out = relu(acc + bias)
// 4 chunks (pass 0/1 x K-half 0/1 of 64), double-buffered A/W slabs;
// chunk c+1 staged via cp.async during chunk c's MMA. 2 CTAs/SM.
// ---------------------------------------------------------------------------
#define PITCH  72
#define ROWB   (PITCH * 2)              // 144 bytes per row
#define SLAB_B (128 * ROWB)             // 18432
#define SMEM_BYTES (4 * SLAB_B)         // 73728 (A0,A1,W0,W1)

// stage chunk: A rows [nb..nb+127] cols [k0..k0+63] + W slab cols [k0..k0+63]
#define STAGE(Aptr, Wptr, k0, buf)                                              \
    do {                                                                        \
        const uint32_t ab_ = smb + (buf) * SLAB_B;                              \
        const uint32_t wb_ = smb + (2 + (buf)) * SLAB_B;                        \
        for (int i_ = t; i_ < 1024; i_ += 256) {                                \
            const int r_ = i_ >> 3, sg_ = i_ & 7;                               \
            cp16(ab_ + r_ * ROWB + sg_ * 16,                                    \
                 (Aptr) + (size_t)(nb + r_) * C + (k0) + sg_ * 8);              \
        }                                                                       \
        for (int i_ = t; i_ < 1024; i_ += 256) {                                \
            const int r_ = i_ >> 3, sg_ = i_ & 7;                               \
            cp16(wb_ + r_ * ROWB + sg_ * 16,                                    \
                 (Wptr) + (size_t)r_ * 128 + (k0) + sg_ * 8);                   \
        }                                                                       \
        asm volatile("cp.async.commit_group;" ::: "memory");                    \
    } while (0)

#define MMAC(buf)                                                               \
    do {                                                                        \
        const uint32_t ab_ = smb + (buf) * SLAB_B;                              \
        const uint32_t wb_ = smb + (2 + (buf)) * SLAB_B;                        \
        _Pragma("unroll")                                                       \
        for (int ks_ = 0; ks_ < 4; ks_++) {                                     \
            uint32_t a0_[4], a1_[4];                                            \
            ldsm4(ab_ + aoff + ks_ * 32, a0_);                                  \
            ldsm4(ab_ + aoff + 16 * ROWB + ks_ * 32, a1_);                      \
            _Pragma("unroll")                                                   \
            for (int p_ = 0; p_ < 4; p_++) {                                    \
                uint32_t b_[4];                                                 \
                ldsm4(wb_ + boff + p_ * (16 * ROWB) + ks_ * 32, b_);            \
                mma16816h(acc[0][2 * p_],     a0_, b_);                         \
                mma16816h(acc[1][2 * p_],     a1_, b_);                         \
                mma16816h(acc[0][2 * p_ + 1], a0_, b_ + 2);                     \
                mma16816h(acc[1][2 * p_ + 1], a1_, b_ + 2);                     \
            }                                                                   \
        }                                                                       \
    } while (0)

__global__ __launch_bounds__(256, 2) void hmma_layer(
    const __half* __restrict__ A1, const __half* __restrict__ A2,
    const __half* __restrict__ wh, int s0, int s1,
    const float* __restrict__ bias,
    float* __restrict__ out32, __half* __restrict__ outh,
    int nrows)
{
    extern __shared__ char sm[];
    const uint32_t smb = smem_u32(sm);
    const int t = threadIdx.x, wid = t >> 5, lane = t & 31;
    const int nb = blockIdx.x * 128;

    const int mBase = (wid & 3) * 32;
    const int nBase = (wid >> 2) * 64;

    const int arow = (lane & 7) + ((lane >> 3) & 1) * 8;
    const int acol = (lane >> 4) * 8;
    const int brow = (lane & 7) + (lane >> 4) * 8;
    const int bcol = ((lane >> 3) & 1) * 8;
    const uint32_t aoff = (uint32_t)(mBase + arow) * ROWB + (uint32_t)acol * 2;
    const uint32_t boff = (uint32_t)(nBase + brow) * ROWB + (uint32_t)bcol * 2;

    const __half* W0 = wh + (size_t)s0 * 16384;
    const __half* W1 = wh + (size_t)s1 * 16384;

    float acc[2][8][4];
#pragma unroll
    for (int mt = 0; mt < 2; mt++)
#pragma unroll
        for (int nt = 0; nt < 8; nt++)
#pragma unroll
            for (int j = 0; j < 4; j++) acc[mt][nt][j] = 0.f;

    STAGE(A1, W0, 0,  0);               // chunk 0 -> buf 0
    STAGE(A1, W0, 64, 1);               // chunk 1 -> buf 1

    asm volatile("cp.async.wait_group 1;" ::: "memory");
    __syncthreads();
    MMAC(0);
    __syncthreads();
    STAGE(A2, W1, 0, 0);                // chunk 2 -> buf 0

    asm volatile("cp.async.wait_group 1;" ::: "memory");
    __syncthreads();
    MMAC(1);
    __syncthreads();
    STAGE(A2, W1, 64, 1);               // chunk 3 -> buf 1

    asm volatile("cp.async.wait_group 1;" ::: "memory");
    __syncthreads();
    MMAC(0);
    __syncthreads();

    asm volatile("cp.async.wait_group 0;" ::: "memory");
    __syncthreads();
    MMAC(1);

    // -- epilogue: bias + relu --
    const int qrow = lane >> 2;
    const int qk   = (lane & 3) * 2;
#pragma unroll
    for (int nt = 0; nt < 8; nt++) {
        const int cl = nBase + nt * 8 + qk;
        const float2 b = __ldg((const float2*)(bias + cl));
#pragma unroll
        for (int mt = 0; mt < 2; mt++) {
#pragma unroll
            for (int half = 0; half < 2; half++) {
                const int r = nb + mBase + mt * 16 + qrow + half * 8;
                if (r < nrows) {
                    float ox = fmaxf(acc[mt][nt][2 * half]     + b.x, 0.f);
                    float oy = fmaxf(acc[mt][nt][2 * half + 1] + b.y, 0.f);
                    const size_t off = (size_t)r * C + cl;
                    if (out32) *(float2*)(out32 + off) = make_float2(ox, oy);
                    if (outh) {
                        __half2 hh = __floats2half2_rn(ox, oy);
                        *(__half2*)(outh + off) = hh;
                    }
                }
            }
        }
    }
}

// ---------------------------------------------------------------------------
// launch
// ---------------------------------------------------------------------------
extern "C" void kernel_launch(void* const* d_in, const int* in_sizes, int n_in,
                              void* d_out, int out_size)
{
    const float* x    = (const float*)d_in[0];
    const int*   ei   = (const int*)  d_in[1];
    const float* Wl1  = (const float*)d_in[2];
    const float* Wr1  = (const float*)d_in[3];
    const float* b1   = (const float*)d_in[4];
    const float* Wl2  = (const float*)d_in[5];
    const float* Wr2  = (const float*)d_in[6];
    const float* b2   = (const float*)d_in[7];
    const float* Wlin = (const float*)d_in[8];
    const float* blin = (const float*)d_in[9];
    float*       out  = (float*)d_out;

    const int* src = ei;
    const int* dst = ei + EE;

    void *xh_v, *aggh_v, *h1h_v, *h2h_v, *wh_v;
    void *cnt_v, *rp_v, *cur_v, *part_v, *srcs_v;
    cudaGetSymbolAddress(&xh_v,   g_xh);
    cudaGetSymbolAddress(&aggh_v, g_aggh);
    cudaGetSymbolAddress(&h1h_v,  g_h1h);
    cudaGetSymbolAddress(&h2h_v,  g_h2h);
    cudaGetSymbolAddress(&wh_v,   g_wh);
    cudaGetSymbolAddress(&cnt_v,  g_cnt);
    cudaGetSymbolAddress(&rp_v,   g_rowptr);
    cudaGetSymbolAddress(&cur_v,  g_cursor);
    cudaGetSymbolAddress(&part_v, g_part);
    cudaGetSymbolAddress(&srcs_v, g_srcs);
    __half* xh   = (__half*)xh_v;
    __half* aggh = (__half*)aggh_v;
    __half* h1h  = (__half*)h1h_v;
    __half* h2h  = (__half*)h2h_v;
    __half* wh   = (__half*)wh_v;
    int* cnt    = (int*)cnt_v;
    int* rowptr = (int*)rp_v;
    int* cursor = (int*)cur_v;
    int* part   = (int*)part_v;
    int* srcs   = (int*)srcs_v;

    cudaFuncSetAttribute(hmma_layer,
                         cudaFuncAttributeMaxDynamicSharedMemorySize, SMEM_BYTES);

    const int eblk = (EE + 255) / 256;           // 6250
    const int gblk = (NN + 127) / 128;           // 782
    const int ablk = (NN + 7) / 8;               // 12500
    const int pblk = (PREP_TOT + 255) / 256;

    // ---- prep (one kernel) + CSR build ----
    prep_all<<<pblk, 256>>>(x, Wl1, Wr1, Wl2, Wr2, Wlin, xh, wh, cnt);
    hist_kernel<<<eblk, 256>>>(dst, cnt);
    scan_blk<<<NB, 1024>>>(cnt, rowptr, part);
    scan_add2<<<NB, 1024>>>(part, rowptr, cursor);
    scatter_csr<<<eblk, 256>>>(src, dst, cursor, srcs);

    // ---- conv1: gather(x) -> aggh; h1 = relu(aggh·Wl1 + x·Wr1 + b1) ----
    aggregate_h<<<ablk, 256>>>(xh, rowptr, srcs, aggh);
    hmma_layer<<<gblk, 256, SMEM_BYTES>>>(aggh, xh, wh, 0, 1, b1, nullptr, h1h, NN);

    // ---- conv2: gather(h1) -> aggh; h2 = relu(aggh·Wl2 + h1·Wr2 + b2) ----
    aggregate_h<<<ablk, 256>>>(h1h, rowptr, srcs, aggh);
    hmma_layer<<<gblk, 256, SMEM_BYTES>>>(aggh, h1h, wh, 2, 3, b2, nullptr, h2h, NN);

    // ---- JK-cat + linear head ----
    hmma_layer<<<gblk, 256, SMEM_BYTES>>>(h1h, h2h, wh, 4, 5, blin, out, nullptr, NN);
}

// round 17
// speedup vs baseline: 1.6763x; 1.0185x over previous
#include <cuda_runtime.h>
#include <cuda_fp16.h>
#include <cstdint>
#include <cstddef>

#define NN 100000
#define EE 1600000
#define C  128
#define NB 98                 // scan blocks: ceil(100000/1024)
#define NP (NN + 128)         // padded rows: edge-tile cp.async stays in-bounds

// ---- scratch (device globals: allocation-free) ----
__device__ __half g_xh  [(size_t)NP * C];
__device__ __half g_aggh[(size_t)NP * C];
__device__ __half g_h1h [(size_t)NP * C];
__device__ __half g_h2h [(size_t)NP * C];
__device__ __half g_wh[6 * 16384];
__device__ int g_cnt[NN];
__device__ int g_rowptr[NN + 1];
__device__ int g_cursor[NN];
__device__ int g_part[NB];
__device__ int g_flag[NB];
__device__ int g_srcs[EE];

// ---------------------------------------------------------------------------
// helpers
// ---------------------------------------------------------------------------
__device__ __forceinline__ uint32_t smem_u32(const void* p) {
    uint32_t a;
    asm("{ .reg .u64 t; cvta.to.shared.u64 t, %1; cvt.u32.u64 %0, t; }"
        : "=r"(a) : "l"(p));
    return a;
}
__device__ __forceinline__ void cp16(uint32_t saddr, const void* g) {
    asm volatile("cp.async.cg.shared.global [%0], [%1], 16;"
                 :: "r"(saddr), "l"(g) : "memory");
}
__device__ __forceinline__ void ldsm4(uint32_t addr, uint32_t* r) {
    asm volatile("ldmatrix.sync.aligned.m8n8.x4.shared.b16 {%0,%1,%2,%3}, [%4];"
                 : "=r"(r[0]), "=r"(r[1]), "=r"(r[2]), "=r"(r[3]) : "r"(addr));
}
__device__ __forceinline__ void mma16816h(float* c, const uint32_t* a, const uint32_t* b) {
    asm volatile(
        "mma.sync.aligned.m16n8k16.row.col.f32.f16.f16.f32 "
        "{%0,%1,%2,%3}, {%4,%5,%6,%7}, {%8,%9}, {%0,%1,%2,%3};"
        : "+f"(c[0]), "+f"(c[1]), "+f"(c[2]), "+f"(c[3])
        : "r"(a[0]), "r"(a[1]), "r"(a[2]), "r"(a[3]), "r"(b[0]), "r"(b[1]));
}
__device__ __forceinline__ int warp_iscan(int v, int lane) {
#pragma unroll
    for (int d = 1; d < 32; d <<= 1) {
        int n = __shfl_up_sync(0xFFFFFFFFu, v, d);
        if (lane >= d) v += n;
    }
    return v;
}

// ---------------------------------------------------------------------------
// fused prep: x->fp16 | weights->fp16 | zero cnt | zero scan flags
// ---------------------------------------------------------------------------
#define N4    (NN * C / 4)                 // 3,200,000 float4 groups
#define WTOT  (6 * 16384)                  // 98,304 weight elems
#define PREP_TOT (N4 + WTOT + NN + NB)

__global__ void prep_all(const float* __restrict__ x,
                         const float* __restrict__ Wl1, const float* __restrict__ Wr1,
                         const float* __restrict__ Wl2, const float* __restrict__ Wr2,
                         const float* __restrict__ Wlin,
                         __half* __restrict__ xh, __half* __restrict__ wh,
                         int* __restrict__ cnt, int* __restrict__ flag)
{
    int i = blockIdx.x * blockDim.x + threadIdx.x;
    if (i < N4) {
        float4 v = __ldg((const float4*)x + i);
        __half2 h0 = __floats2half2_rn(v.x, v.y);
        __half2 h1 = __floats2half2_rn(v.z, v.w);
        *(uint2*)(xh + (size_t)i * 4) = make_uint2(*(uint32_t*)&h0, *(uint32_t*)&h1);
    } else if (i < N4 + WTOT) {
        int j = i - N4;
        int s = j >> 14, r = (j >> 7) & 127, k = j & 127;
        float v;
        switch (s) {
            case 0:  v = __ldg(Wl1 + r * 128 + k); break;
            case 1:  v = __ldg(Wr1 + r * 128 + k); break;
            case 2:  v = __ldg(Wl2 + r * 128 + k); break;
            case 3:  v = __ldg(Wr2 + r * 128 + k); break;
            case 4:  v = __ldg(Wlin + r * 256 + k); break;
            default: v = __ldg(Wlin + r * 256 + 128 + k); break;
        }
        wh[j] = __float2half_rn(v);
    } else if (i < N4 + WTOT + NN) {
        cnt[i - N4 - WTOT] = 0;
    } else if (i < PREP_TOT) {
        flag[i - N4 - WTOT - NN] = 0;
    }
}

// ---------------------------------------------------------------------------
// CSR build: histogram -> single-launch decoupled-lookback scan -> scatter
// ---------------------------------------------------------------------------
__global__ void hist_kernel(const int* __restrict__ dst, int* __restrict__ cnt) {
    int e = blockIdx.x * blockDim.x + threadIdx.x;
    if (e < EE) atomicAdd(cnt + __ldg(dst + e), 1);
}

// one launch: local block scan + publish partial + lookback over predecessors
// Safe: 98 blocks < 148 SMs -> all resident; block b only waits on blocks < b.
__global__ __launch_bounds__(1024) void scan_chain(
    const int* __restrict__ cnt, int* __restrict__ rowptr, int* __restrict__ cursor,
    int* __restrict__ part, int* __restrict__ flag)
{
    __shared__ int ws[32];
    __shared__ int sp[128];
    __shared__ int off_s;
    const int b = blockIdx.x;
    const int t = threadIdx.x, lane = t & 31, w = t >> 5;
    const int i = b * 1024 + t;
    const int v = (i < NN) ? __ldg(cnt + i) : 0;

    int x = warp_iscan(v, lane);
    if (lane == 31) ws[w] = x;
    __syncthreads();
    if (w == 0) ws[lane] = warp_iscan(ws[lane], lane);
    __syncthreads();
    const int incl = x + (w ? ws[w - 1] : 0);
    const int excl = incl - v;

    // publish this block's total (partial), then flag
    if (t == 1023) {
        part[b] = incl;
        __threadfence();
        flag[b] = 1;
    }

    // lookback: thread t polls predecessor t (t < b <= 97)
    if (t < 128) sp[t] = 0;
    __syncthreads();
    if (t < b) {
        volatile int* vf = (volatile int*)flag;
        while (vf[t] == 0) {}
        sp[t] = *((volatile int*)(part + t));
    }
    __syncthreads();
    if (w == 0) {
        int s4 = sp[lane] + sp[lane + 32] + sp[lane + 64] + sp[lane + 96];
#pragma unroll
        for (int d = 16; d > 0; d >>= 1)
            s4 += __shfl_down_sync(0xFFFFFFFFu, s4, d);
        if (lane == 0) off_s = s4;
    }
    __syncthreads();

    if (i < NN) {
        const int r = excl + off_s;
        rowptr[i] = r;
        cursor[i] = r;
    }
    if (i == 0) rowptr[NN] = EE;
}

__global__ void scatter_csr(const int* __restrict__ src, const int* __restrict__ dst,
                            int* __restrict__ cursor, int* __restrict__ srcs)
{
    int e = blockIdx.x * blockDim.x + threadIdx.x;
    if (e >= EE) return;
    int d = __ldg(dst + e);
    int pos = atomicAdd(cursor + d, 1);
    srcs[pos] = __ldg(src + e);
}

// ---------------------------------------------------------------------------
// atomic-free mean aggregation: 2 nodes per warp (16 lanes x uint4 = 256B/row),
// fp32 accumulate, fp16 out. Same per-feature summation order as before.
// ---------------------------------------------------------------------------
__global__ __launch_bounds__(256) void aggregate_h(
    const __half* __restrict__ feat16,
    const int*    __restrict__ rowptr,
    const int*    __restrict__ srcs,
    __half*       __restrict__ aggh)
{
    const int warp = threadIdx.x >> 5;
    const int lane = threadIdx.x & 31;
    const int half = lane >> 4;          // which of the warp's 2 nodes
    const int hl   = lane & 15;          // lane within node group
    const int node = blockIdx.x * 16 + warp * 2 + half;
    if (node >= NN) return;

    const int beg = __ldg(rowptr + node);
    const int end = __ldg(rowptr + node + 1);

    const uint4* fb = (const uint4*)feat16 + hl;   // row = 16 uint4

    float a[8];
#pragma unroll
    for (int j = 0; j < 8; j++) a[j] = 0.f;

    int e = beg;
    for (; e + 8 <= end; e += 8) {
        int s[8];
#pragma unroll
        for (int j = 0; j < 8; j++) s[j] = __ldg(srcs + e + j);
        uint4 u[8];
#pragma unroll
        for (int j = 0; j < 8; j++) u[j] = __ldg(fb + (size_t)s[j] * 16);
#pragma unroll
        for (int j = 0; j < 8; j++) {
            float2 f0 = __half22float2(*(__half2*)&u[j].x);
            float2 f1 = __half22float2(*(__half2*)&u[j].y);
            float2 f2 = __half22float2(*(__half2*)&u[j].z);
            float2 f3 = __half22float2(*(__half2*)&u[j].w);
            a[0] += f0.x; a[1] += f0.y; a[2] += f1.x; a[3] += f1.y;
            a[4] += f2.x; a[5] += f2.y; a[6] += f3.x; a[7] += f3.y;
        }
    }
    for (; e < end; e++) {
        int s0 = __ldg(srcs + e);
        uint4 u = __ldg(fb + (size_t)s0 * 16);
        float2 f0 = __half22float2(*(__half2*)&u.x);
        float2 f1 = __half22float2(*(__half2*)&u.y);
        float2 f2 = __half22float2(*(__half2*)&u.z);
        float2 f3 = __half22float2(*(__half2*)&u.w);
        a[0] += f0.x; a[1] += f0.y; a[2] += f1.x; a[3] += f1.y;
        a[4] += f2.x; a[5] += f2.y; a[6] += f3.x; a[7] += f3.y;
    }

    const int deg = end - beg;
    const float inv = 1.f / (float)(deg > 1 ? deg : 1);
    __half2 o0 = __floats2half2_rn(a[0] * inv, a[1] * inv);
    __half2 o1 = __floats2half2_rn(a[2] * inv, a[3] * inv);
    __half2 o2 = __floats2half2_rn(a[4] * inv, a[5] * inv);
    __half2 o3 = __floats2half2_rn(a[6] * inv, a[7] * inv);
    uint4 o;
    o.x = *(uint32_t*)&o0; o.y = *(uint32_t*)&o1;
    o.z = *(uint32_t*)&o2; o.w = *(uint32_t*)&o3;
    *((uint4*)(aggh + (size_t)node * C) + hl) = o;
}

// ---------------------------------------------------------------------------
// fp16 HMMA fused dual-matmul layer, software-pipelined (round-14, passing)
// ---------------------------------------------------------------------------
#define PITCH  72
#define ROWB   (PITCH * 2)              // 144 bytes per row
#define SLAB_B (128 * ROWB)             // 18432
#define SMEM_BYTES (4 * SLAB_B)         // 73728 (A0,A1,W0,W1)

#define STAGE(Aptr, Wptr, k0, buf)                                              \
    do {                                                                        \
        const uint32_t ab_ = smb + (buf) * SLAB_B;                              \
        const uint32_t wb_ = smb + (2 + (buf)) * SLAB_B;                        \
        for (int i_ = t; i_ < 1024; i_ += 256) {                                \
            const int r_ = i_ >> 3, sg_ = i_ & 7;                               \
            cp16(ab_ + r_ * ROWB + sg_ * 16,                                    \
                 (Aptr) + (size_t)(nb + r_) * C + (k0) + sg_ * 8);              \
        }                                                                       \
        for (int i_ = t; i_ < 1024; i_ += 256) {                                \
            const int r_ = i_ >> 3, sg_ = i_ & 7;                               \
            cp16(wb_ + r_ * ROWB + sg_ * 16,                                    \
                 (Wptr) + (size_t)r_ * 128 + (k0) + sg_ * 8);                   \
        }                                                                       \
        asm volatile("cp.async.commit_group;" ::: "memory");                    \
    } while (0)

#define MMAC(buf)                                                               \
    do {                                                                        \
        const uint32_t ab_ = smb + (buf) * SLAB_B;                              \
        const uint32_t wb_ = smb + (2 + (buf)) * SLAB_B;                        \
        _Pragma("unroll")                                                       \
        for (int ks_ = 0; ks_ < 4; ks_++) {                                     \
            uint32_t a0_[4], a1_[4];                                            \
            ldsm4(ab_ + aoff + ks_ * 32, a0_);                                  \
            ldsm4(ab_ + aoff + 16 * ROWB + ks_ * 32, a1_);                      \
            _Pragma("unroll")                                                   \
            for (int p_ = 0; p_ < 4; p_++) {                                    \
                uint32_t b_[4];                                                 \
                ldsm4(wb_ + boff + p_ * (16 * ROWB) + ks_ * 32, b_);            \
                mma16816h(acc[0][2 * p_],     a0_, b_);                         \
                mma16816h(acc[1][2 * p_],     a1_, b_);                         \
                mma16816h(acc[0][2 * p_ + 1], a0_, b_ + 2);                     \
                mma16816h(acc[1][2 * p_ + 1], a1_, b_ + 2);                     \
            }                                                                   \
        }                                                                       \
    } while (0)

__global__ __launch_bounds__(256, 2) void hmma_layer(
    const __half* __restrict__ A1, const __half* __restrict__ A2,
    const __half* __restrict__ wh, int s0, int s1,
    const float* __restrict__ bias,
    float* __restrict__ out32, __half* __restrict__ outh,
    int nrows)
{
    extern __shared__ char sm[];
    const uint32_t smb = smem_u32(sm);
    const int t = threadIdx.x, wid = t >> 5, lane = t & 31;
    const int nb = blockIdx.x * 128;

    const int mBase = (wid & 3) * 32;
    const int nBase = (wid >> 2) * 64;

    const int arow = (lane & 7) + ((lane >> 3) & 1) * 8;
    const int acol = (lane >> 4) * 8;
    const int brow = (lane & 7) + (lane >> 4) * 8;
    const int bcol = ((lane >> 3) & 1) * 8;
    const uint32_t aoff = (uint32_t)(mBase + arow) * ROWB + (uint32_t)acol * 2;
    const uint32_t boff = (uint32_t)(nBase + brow) * ROWB + (uint32_t)bcol * 2;

    const __half* W0 = wh + (size_t)s0 * 16384;
    const __half* W1 = wh + (size_t)s1 * 16384;

    float acc[2][8][4];
#pragma unroll
    for (int mt = 0; mt < 2; mt++)
#pragma unroll
        for (int nt = 0; nt < 8; nt++)
#pragma unroll
            for (int j = 0; j < 4; j++) acc[mt][nt][j] = 0.f;

    STAGE(A1, W0, 0,  0);
    STAGE(A1, W0, 64, 1);

    asm volatile("cp.async.wait_group 1;" ::: "memory");
    __syncthreads();
    MMAC(0);
    __syncthreads();
    STAGE(A2, W1, 0, 0);

    asm volatile("cp.async.wait_group 1;" ::: "memory");
    __syncthreads();
    MMAC(1);
    __syncthreads();
    STAGE(A2, W1, 64, 1);

    asm volatile("cp.async.wait_group 1;" ::: "memory");
    __syncthreads();
    MMAC(0);
    __syncthreads();

    asm volatile("cp.async.wait_group 0;" ::: "memory");
    __syncthreads();
    MMAC(1);

    // -- epilogue: bias + relu --
    const int qrow = lane >> 2;
    const int qk   = (lane & 3) * 2;
#pragma unroll
    for (int nt = 0; nt < 8; nt++) {
        const int cl = nBase + nt * 8 + qk;
        const float2 b = __ldg((const float2*)(bias + cl));
#pragma unroll
        for (int mt = 0; mt < 2; mt++) {
#pragma unroll
            for (int half = 0; half < 2; half++) {
                const int r = nb + mBase + mt * 16 + qrow + half * 8;
                if (r < nrows) {
                    float ox = fmaxf(acc[mt][nt][2 * half]     + b.x, 0.f);
                    float oy = fmaxf(acc[mt][nt][2 * half + 1] + b.y, 0.f);
                    const size_t off = (size_t)r * C + cl;
                    if (out32) *(float2*)(out32 + off) = make_float2(ox, oy);
                    if (outh) {
                        __half2 hh = __floats2half2_rn(ox, oy);
                        *(__half2*)(outh + off) = hh;
                    }
                }
            }
        }
    }
}

// ---------------------------------------------------------------------------
// launch
// ---------------------------------------------------------------------------
extern "C" void kernel_launch(void* const* d_in, const int* in_sizes, int n_in,
                              void* d_out, int out_size)
{
    const float* x    = (const float*)d_in[0];
    const int*   ei   = (const int*)  d_in[1];
    const float* Wl1  = (const float*)d_in[2];
    const float* Wr1  = (const float*)d_in[3];
    const float* b1   = (const float*)d_in[4];
    const float* Wl2  = (const float*)d_in[5];
    const float* Wr2  = (const float*)d_in[6];
    const float* b2   = (const float*)d_in[7];
    const float* Wlin = (const float*)d_in[8];
    const float* blin = (const float*)d_in[9];
    float*       out  = (float*)d_out;

    const int* src = ei;
    const int* dst = ei + EE;

    void *xh_v, *aggh_v, *h1h_v, *h2h_v, *wh_v;
    void *cnt_v, *rp_v, *cur_v, *part_v, *flag_v, *srcs_v;
    cudaGetSymbolAddress(&xh_v,   g_xh);
    cudaGetSymbolAddress(&aggh_v, g_aggh);
    cudaGetSymbolAddress(&h1h_v,  g_h1h);
    cudaGetSymbolAddress(&h2h_v,  g_h2h);
    cudaGetSymbolAddress(&wh_v,   g_wh);
    cudaGetSymbolAddress(&cnt_v,  g_cnt);
    cudaGetSymbolAddress(&rp_v,   g_rowptr);
    cudaGetSymbolAddress(&cur_v,  g_cursor);
    cudaGetSymbolAddress(&part_v, g_part);
    cudaGetSymbolAddress(&flag_v, g_flag);
    cudaGetSymbolAddress(&srcs_v, g_srcs);
    __half* xh   = (__half*)xh_v;
    __half* aggh = (__half*)aggh_v;
    __half* h1h  = (__half*)h1h_v;
    __half* h2h  = (__half*)h2h_v;
    __half* wh   = (__half*)wh_v;
    int* cnt    = (int*)cnt_v;
    int* rowptr = (int*)rp_v;
    int* cursor = (int*)cur_v;
    int* part   = (int*)part_v;
    int* flag   = (int*)flag_v;
    int* srcs   = (int*)srcs_v;

    cudaFuncSetAttribute(hmma_layer,
                         cudaFuncAttributeMaxDynamicSharedMemorySize, SMEM_BYTES);

    const int eblk = (EE + 255) / 256;           // 6250
    const int gblk = (NN + 127) / 128;           // 782
    const int ablk = (NN + 15) / 16;             // 6250
    const int pblk = (PREP_TOT + 255) / 256;

    // ---- prep (one kernel) + CSR build ----
    prep_all<<<pblk, 256>>>(x, Wl1, Wr1, Wl2, Wr2, Wlin, xh, wh, cnt, flag);
    hist_kernel<<<eblk, 256>>>(dst, cnt);
    scan_chain<<<NB, 1024>>>(cnt, rowptr, cursor, part, flag);
    scatter_csr<<<eblk, 256>>>(src, dst, cursor, srcs);

    // ---- conv1: gather(x) -> aggh; h1 = relu(aggh·Wl1 + x·Wr1 + b1) ----
    aggregate_h<<<ablk, 256>>>(xh, rowptr, srcs, aggh);
    hmma_layer<<<gblk, 256, SMEM_BYTES>>>(aggh, xh, wh, 0, 1, b1, nullptr, h1h, NN);

    // ---- conv2: gather(h1) -> aggh; h2 = relu(aggh·Wl2 + h1·Wr2 + b2) ----
    aggregate_h<<<ablk, 256>>>(h1h, rowptr, srcs, aggh);
    hmma_layer<<<gblk, 256, SMEM_BYTES>>>(aggh, h1h, wh, 2, 3, b2, nullptr, h2h, NN);

    // ---- JK-cat + linear head ----
    hmma_layer<<<gblk, 256, SMEM_BYTES>>>(h1h, h2h, wh, 4, 5, blin, out, nullptr, NN);
}